// round 4
// baseline (speedup 1.0000x reference)
#include <cuda_runtime.h>
#include <cuda_bf16.h>
#include <cstdint>

// out[t, :] = W[x[t], :] + b    t in [0, 8192), D = 2048
// Persistent CTAs + cp.async.bulk (TMA bulk engine) row gather, depth-3 ring.
// Loads bypass the L1tex/register path that capped LDG at ~4 TB/s.

#define D_MODEL 2048
#define D4      (D_MODEL / 4)      // 512 float4 per row
#define ROW_BYTES (D_MODEL * 4)    // 8192 B
#define NBUF    3
#define GRID    592                // 4 CTAs/SM on 148 SMs
#define NTHR    256

__device__ __forceinline__ uint32_t smem_u32(const void* p) {
    uint32_t a;
    asm("{ .reg .u64 t; cvta.to.shared.u64 t, %1; cvt.u32.u64 %0, t; }"
        : "=r"(a) : "l"(p));
    return a;
}

__device__ __forceinline__ void mbar_init(uint32_t mbar, uint32_t count) {
    asm volatile("mbarrier.init.shared.b64 [%0], %1;" :: "r"(mbar), "r"(count) : "memory");
}

__device__ __forceinline__ void mbar_expect_tx(uint32_t mbar, uint32_t bytes) {
    asm volatile("mbarrier.arrive.expect_tx.shared.b64 _, [%0], %1;"
                 :: "r"(mbar), "r"(bytes) : "memory");
}

__device__ __forceinline__ void bulk_load(uint32_t smem_dst, const void* gmem_src,
                                          uint32_t bytes, uint32_t mbar) {
    asm volatile(
        "cp.async.bulk.shared::cluster.global.mbarrier::complete_tx::bytes "
        "[%0], [%1], %2, [%3];"
        :: "r"(smem_dst), "l"(gmem_src), "r"(bytes), "r"(mbar) : "memory");
}

__device__ __forceinline__ void mbar_wait(uint32_t mbar, uint32_t parity) {
    uint32_t done;
    asm volatile(
        "{\n\t.reg .pred p;\n\t"
        "mbarrier.try_wait.parity.acquire.cta.shared::cta.b64 p, [%1], %2;\n\t"
        "selp.b32 %0, 1, 0, p;\n\t}"
        : "=r"(done) : "r"(mbar), "r"(parity) : "memory");
    if (!done) {
        asm volatile(
            "{\n\t.reg .pred P1;\n\t"
            "WL_%=:\n\t"
            "mbarrier.try_wait.parity.acquire.cta.shared::cta.b64 P1, [%0], %1, 0x989680;\n\t"
            "@P1 bra.uni WD_%=;\n\t"
            "bra.uni WL_%=;\n\t"
            "WD_%=:\n\t}"
            :: "r"(mbar), "r"(parity) : "memory");
    }
}

__global__ __launch_bounds__(NTHR)
void embed_gather_tma(const int* __restrict__ x,
                      const char* __restrict__ W,      // byte pointer to rows
                      const float4* __restrict__ b4,
                      float4* __restrict__ out4,
                      int tokens) {
    __shared__ alignas(128) float4 buf[NBUF][D4];
    __shared__ alignas(8) unsigned long long mbar_s[NBUF];

    const int tid = threadIdx.x;
    const int bid = blockIdx.x;

    uint32_t mb[NBUF];
#pragma unroll
    for (int k = 0; k < NBUF; k++) mb[k] = smem_u32(&mbar_s[k]);
    uint32_t bufa[NBUF];
#pragma unroll
    for (int k = 0; k < NBUF; k++) bufa[k] = smem_u32(&buf[k][0]);

    if (tid == 0) {
#pragma unroll
        for (int k = 0; k < NBUF; k++) mbar_init(mb[k], 1);
    }
    __syncthreads();

    // bias: each thread owns columns tid and tid+256 for every token
    const int c0 = tid;
    const int c1 = tid + NTHR;
    const float4 bb0 = b4[c0];
    const float4 bb1 = b4[c1];

    // prologue: fill the ring
    if (tid == 0) {
#pragma unroll
        for (int k = 0; k < NBUF; k++) {
            int t = bid + k * GRID;
            if (t < tokens) {
                long long row = (long long)__ldg(x + t);
                mbar_expect_tx(mb[k], ROW_BYTES);
                bulk_load(bufa[k], W + row * ROW_BYTES, ROW_BYTES, mb[k]);
            }
        }
    }

    int i = 0;
    for (int t = bid; t < tokens; t += GRID, i++) {
        const int p = i % NBUF;
        const uint32_t parity = (uint32_t)((i / NBUF) & 1);
        mbar_wait(mb[p], parity);

        float4 v0 = buf[p][c0];
        float4 v1 = buf[p][c1];
        v0.x += bb0.x; v0.y += bb0.y; v0.z += bb0.z; v0.w += bb0.w;
        v1.x += bb1.x; v1.y += bb1.y; v1.z += bb1.z; v1.w += bb1.w;

        float4* __restrict__ dst = out4 + (long long)t * D4;
        dst[c0] = v0;
        dst[c1] = v1;

        __syncthreads();   // all threads done reading buf[p]

        if (tid == 0) {
            int tn = t + NBUF * GRID;
            if (tn < tokens) {
                long long row = (long long)__ldg(x + tn);
                mbar_expect_tx(mb[p], ROW_BYTES);
                bulk_load(bufa[p], W + row * ROW_BYTES, ROW_BYTES, mb[p]);
            }
        }
    }
}

extern "C" void kernel_launch(void* const* d_in, const int* in_sizes, int n_in,
                              void* d_out, int out_size) {
    const int*    x = (const int*)d_in[0];        // [4, 2048] int32
    const char*   W = (const char*)d_in[1];       // [50257, 2048] f32 as bytes
    const float4* b = (const float4*)d_in[2];     // [2048] f32
    float4* out = (float4*)d_out;                 // [4, 2048, 2048] f32
    const int tokens = in_sizes[0];               // 8192

    embed_gather_tma<<<GRID, NTHR>>>(x, W, b, out, tokens);
}

// round 5
// speedup vs baseline: 1.2327x; 1.2327x over previous
#include <cuda_runtime.h>
#include <cuda_bf16.h>

// out[t, :] = W[x[t], :] + b   for t in [0, 8192), D = 2048
// x: int32 [8192], W: f32 [50257, 2048], b: f32 [2048]
//
// Key insight: steady-state working set (~60 MB touched W rows + 64 MB output)
// sits exactly at the 126 MB L2 capacity cliff. Default write-allocate output
// stores thrash W out of L2 (~82 MB/replay DRAM traffic measured). Fix: mark
// output stores evict-first (.cs) so W stays L2-resident across graph replays;
// DRAM then carries only the output stream.

#define D_MODEL 2048
#define D4      (D_MODEL / 4)   // 512 float4 per row
#define TOKENS  8192

__global__ __launch_bounds__(256, 8)
void embed_gather_kernel(const int* __restrict__ x,
                         const float4* __restrict__ W4,
                         const float4* __restrict__ b4,
                         float4* __restrict__ out4) {
    const int t = blockIdx.x;                         // token index
    const long long row = (long long)x[t];            // vocab row (uniform per block)
    const float4* __restrict__ src = W4 + row * D4;
    float4* __restrict__ dst = out4 + (long long)t * D4;

    const int i0 = threadIdx.x;
    const int i1 = threadIdx.x + 256;

    float4 v0 = src[i0];         // LDG.128 (.ca) — keep W in L2
    float4 v1 = src[i1];
    float4 bb0 = b4[i0];
    float4 bb1 = b4[i1];

    v0.x += bb0.x; v0.y += bb0.y; v0.z += bb0.z; v0.w += bb0.w;
    v1.x += bb1.x; v1.y += bb1.y; v1.z += bb1.z; v1.w += bb1.w;

    __stcs(dst + i0, v0);        // STG.128.CS — evict-first, don't thrash L2
    __stcs(dst + i1, v1);
}

extern "C" void kernel_launch(void* const* d_in, const int* in_sizes, int n_in,
                              void* d_out, int out_size) {
    const int*    x = (const int*)d_in[0];        // [4, 2048] int32
    const float4* W = (const float4*)d_in[1];     // [50257, 2048] f32
    const float4* b = (const float4*)d_in[2];     // [2048] f32
    float4* out = (float4*)d_out;                 // [4, 2048, 2048] f32

    embed_gather_kernel<<<TOKENS, 256>>>(x, W, b, out);
}

// round 7
// speedup vs baseline: 1.3559x; 1.1000x over previous
#include <cuda_runtime.h>
#include <cuda_bf16.h>

// out[t, :] = W[x[t], :] + b   for t in [0, 8192), D = 2048
// x: int32 [8192], W: f32 [50257, 2048], b: f32 [2048]
//
// Model: W is L2-resident across graph replays (~77 MB/replay DRAM = mostly
// output writes). Kernel is long-scoreboard latency-bound (occ 79%, issue 11%,
// DRAM 48%). Fix: MLP=4 per thread (2 tokens/CTA x 2 float4), front-batched,
// staying under the per-CTA L1tex queue cap (8 warps * 4 LDG * 4 lines = 128 < 248).
// R3's MLP=8 overflowed it (256 > 248) and regressed.

#define D_MODEL 2048
#define D4      (D_MODEL / 4)   // 512 float4 per row
#define TOKENS  8192
#define TPC     2

__global__ __launch_bounds__(256, 8)
void embed_gather_kernel(const int* __restrict__ x,
                         const float4* __restrict__ W4,
                         const float4* __restrict__ b4,
                         float4* __restrict__ out4) {
    const int t0 = blockIdx.x * TPC;

    // independent index loads first
    const long long r0 = (long long)x[t0 + 0];
    const long long r1 = (long long)x[t0 + 1];

    const int c0 = threadIdx.x;
    const int c1 = threadIdx.x + 256;

    const float4 bb0 = b4[c0];
    const float4 bb1 = b4[c1];

    // 4 independent W gathers, front-batched
    float4 v00 = W4[r0 * D4 + c0];
    float4 v01 = W4[r0 * D4 + c1];
    float4 v10 = W4[r1 * D4 + c0];
    float4 v11 = W4[r1 * D4 + c1];

    v00.x += bb0.x; v00.y += bb0.y; v00.z += bb0.z; v00.w += bb0.w;
    v01.x += bb1.x; v01.y += bb1.y; v01.z += bb1.z; v01.w += bb1.w;
    v10.x += bb0.x; v10.y += bb0.y; v10.z += bb0.z; v10.w += bb0.w;
    v11.x += bb1.x; v11.y += bb1.y; v11.z += bb1.z; v11.w += bb1.w;

    float4* __restrict__ dst = out4 + (long long)t0 * D4;
    __stcs(dst + c0, v00);           // evict-first: don't thrash W out of L2
    __stcs(dst + c1, v01);
    __stcs(dst + D4 + c0, v10);
    __stcs(dst + D4 + c1, v11);
}

extern "C" void kernel_launch(void* const* d_in, const int* in_sizes, int n_in,
                              void* d_out, int out_size) {
    const int*    x = (const int*)d_in[0];        // [4, 2048] int32
    const float4* W = (const float4*)d_in[1];     // [50257, 2048] f32
    const float4* b = (const float4*)d_in[2];     // [2048] f32
    float4* out = (float4*)d_out;                 // [4, 2048, 2048] f32

    embed_gather_kernel<<<TOKENS / TPC, 256>>>(x, W, b, out);
}